// round 11
// baseline (speedup 1.0000x reference)
#include <cuda_runtime.h>
#include <cuda_bf16.h>

#define BATCH 16
#define NN    1024
#define DD    64
#define EPSF      0.1f
#define INV_EPS   10.0f
#define LOG_MU   (-6.9314616f)   // log(1/1024 + 1e-8)
#define THRESH    0.1f
#define MAX_ITER  100
#define GB        128            // flat persistent grid: 128 blocks <= 148 SMs (co-resident)
#define TB        1024

// ---------------- device scratch (static: no allocations allowed) ----------------
__device__ __nv_bfloat16 g_Kh[BATCH * NN * NN];  // 32 MB: K = exp(-C/eps), bf16
__device__ float g_xs[BATCH * NN * DD];
__device__ float g_ys[BATCH * NN * DD];
__device__ float g_x2[BATCH * NN];
__device__ float g_y2[BATCH * NN];
__device__ float g_u [BATCH * NN];
__device__ float g_v [BATCH * NN];
__device__ float g_a [BATCH * NN];        // exp(u/eps)
__device__ float g_b [BATCH * NN];        // exp(v/eps)
__device__ float g_errA[MAX_ITER * BATCH];
__device__ int      g_itcnt[MAX_ITER];    // batches done with row phase of iteration it
__device__ int      g_verdict[MAX_ITER];  // 0=unset 1=continue 2=stop
__device__ int      g_fin;
__device__ double   g_cost;
__device__ unsigned g_bcnt[BATCH * 32];   // per-batch barrier count (128B padded)
__device__ unsigned g_bgen[BATCH * 32];   // per-batch barrier generation

// ---------------- per-batch barrier: 8 co-resident blocks of one batch ----------------
__device__ __forceinline__ void batch_barrier(int batch) {
    __threadfence();
    __syncthreads();
    if (threadIdx.x == 0) {
        unsigned* cnt = &g_bcnt[batch * 32];
        volatile unsigned* gen = (volatile unsigned*)&g_bgen[batch * 32];
        unsigned g = *gen;
        if (atomicAdd(cnt, 1u) == 7u) {
            *cnt = 0u;
            __threadfence();
            *gen = g + 1u;
        } else {
            while (*gen == g) { __nanosleep(32); }
        }
    }
    __syncthreads();
}

__device__ __forceinline__ float to_tf32(float x) {
    asm("cvt.rna.tf32.f32 %0, %0;" : "+f"(x));
    return x;
}

// dot of 8 bf16 (one uint4) with 8 floats (two float4)
__device__ __forceinline__ float dot8(uint4 q, float4 b0, float4 b1) {
    float2 p0 = __bfloat1622float2(*(const __nv_bfloat162*)&q.x);
    float2 p1 = __bfloat1622float2(*(const __nv_bfloat162*)&q.y);
    float2 p2 = __bfloat1622float2(*(const __nv_bfloat162*)&q.z);
    float2 p3 = __bfloat1622float2(*(const __nv_bfloat162*)&q.w);
    return p0.x*b0.x + p0.y*b0.y + p1.x*b0.z + p1.y*b0.w
         + p2.x*b1.x + p2.y*b1.y + p3.x*b1.z + p3.y*b1.w;
}

// sum of k*b*ln(k) over 8 bf16 k's
__device__ __forceinline__ float dot8log(uint4 q, float4 b0, float4 b1) {
    float2 p0 = __bfloat1622float2(*(const __nv_bfloat162*)&q.x);
    float2 p1 = __bfloat1622float2(*(const __nv_bfloat162*)&q.y);
    float2 p2 = __bfloat1622float2(*(const __nv_bfloat162*)&q.z);
    float2 p3 = __bfloat1622float2(*(const __nv_bfloat162*)&q.w);
    return p0.x*b0.x*__logf(p0.x) + p0.y*b0.y*__logf(p0.y)
         + p1.x*b0.z*__logf(p1.x) + p1.y*b0.w*__logf(p1.y)
         + p2.x*b1.x*__logf(p2.x) + p2.y*b1.y*__logf(p2.y)
         + p3.x*b1.z*__logf(p3.x) + p3.y*b1.w*__logf(p3.y);
}

// ---------------- softmax (D=64): 2 rows per warp, float4, 16-lane trees + init ----------------
__global__ void softmax_kernel(const float* __restrict__ x, const float* __restrict__ y) {
    int gidx = blockIdx.x * blockDim.x + threadIdx.x;
    if (gidx < BATCH * NN) { g_u[gidx] = 0.f; g_v[gidx] = 0.f; g_a[gidx] = 1.f; g_b[gidx] = 1.f; }
    if (gidx < MAX_ITER * BATCH) g_errA[gidx] = 0.f;
    if (gidx < MAX_ITER) { g_itcnt[gidx] = 0; g_verdict[gidx] = 0; }
    if (gidx < BATCH * 32) { g_bcnt[gidx] = 0u; g_bgen[gidx] = 0u; }
    if (gidx == 0) { g_cost = 0.0; g_fin = 0; }

    int gwarp = gidx >> 5;
    int lane  = threadIdx.x & 31;
    int half  = lane >> 4;             // two rows per warp, 16 lanes each
    int hl    = lane & 15;
    int row2  = gwarp * 2 + half;      // 0 .. 2*BATCH*NN-1
    const float* src; float* dst; float* nrm; int row;
    if (row2 < BATCH * NN) { src = x; dst = g_xs; nrm = g_x2; row = row2; }
    else                   { src = y; dst = g_ys; nrm = g_y2; row = row2 - BATCH * NN; }

    float4 e = ((const float4*)(src + (size_t)row * DD))[hl];
    float m = fmaxf(fmaxf(e.x, e.y), fmaxf(e.z, e.w));
    #pragma unroll
    for (int o = 8; o; o >>= 1) m = fmaxf(m, __shfl_xor_sync(0xFFFFFFFFu, m, o));
    float s0 = __expf(e.x - m), s1 = __expf(e.y - m);
    float s2 = __expf(e.z - m), s3 = __expf(e.w - m);
    float s = (s0 + s1) + (s2 + s3);
    #pragma unroll
    for (int o = 8; o; o >>= 1) s += __shfl_xor_sync(0xFFFFFFFFu, s, o);
    float inv = 1.0f / s;
    float4 p = make_float4(s0 * inv, s1 * inv, s2 * inv, s3 * inv);
    ((float4*)(dst + (size_t)row * DD))[hl] = p;
    float q = (p.x * p.x + p.y * p.y) + (p.z * p.z + p.w * p.w);
    #pragma unroll
    for (int o = 8; o; o >>= 1) q += __shfl_xor_sync(0xFFFFFFFFu, q, o);
    if (hl == 0) nrm[row] = q;
}

// ---------------- K = exp((2 x.y - |x|^2 - |y|^2)/eps): 64(i) x 256(j) per block ----------------
// x panel loaded ONCE; y streamed in four 64-col chunks (cuts L2 reads 128MB -> 80MB).
#define XS_STRIDE 68   // (row*68+col)%32 = (row*4+col)%32 -> conflict-free fragment LDS
__global__ void __launch_bounds__(256) buildK_mma() {
    __shared__ float xs[64 * XS_STRIDE];
    __shared__ float ys[64 * XS_STRIDE];
    __shared__ float x2s[64], y2s[64];

    int bx = blockIdx.x;               // 1024 blocks: 16 batch x 16 i-panel x 4 j-group
    int batch = bx >> 6;
    int rem   = bx & 63;
    int i0 = (rem >> 2) * 64;
    int j0base = (rem & 3) * 256;
    int t = threadIdx.x;
    int w = t >> 5, lane = t & 31;
    int mo = (w >> 1) * 16;
    int no = (w & 1) * 32;
    int gr = lane >> 2, gc = lane & 3;

    // load x panel once (tf32-converted)
    const float4* xsrc = (const float4*)(g_xs + (size_t)(batch * NN + i0) * DD);
    #pragma unroll
    for (int k = 0; k < 4; k++) {
        int lin = k * 256 + t;
        int row = lin >> 4, c = (lin & 15) * 4;
        float4 vx = xsrc[lin];
        vx.x = to_tf32(vx.x); vx.y = to_tf32(vx.y); vx.z = to_tf32(vx.z); vx.w = to_tf32(vx.w);
        *((float4*)(xs + row * XS_STRIDE + c)) = vx;
    }
    if (t < 64) x2s[t] = g_x2[batch * NN + i0 + t];

    __nv_bfloat16* Kb = g_Kh + (size_t)batch * NN * NN;

    for (int jc = 0; jc < 4; jc++) {
        int j0 = j0base + jc * 64;
        __syncthreads();               // ys free (and xs ready on jc=0)
        const float4* ysrc = (const float4*)(g_ys + (size_t)(batch * NN + j0) * DD);
        #pragma unroll
        for (int k = 0; k < 4; k++) {
            int lin = k * 256 + t;
            int row = lin >> 4, c = (lin & 15) * 4;
            float4 vy = ysrc[lin];
            vy.x = to_tf32(vy.x); vy.y = to_tf32(vy.y); vy.z = to_tf32(vy.z); vy.w = to_tf32(vy.w);
            *((float4*)(ys + row * XS_STRIDE + c)) = vy;
        }
        if (t < 64) y2s[t] = g_y2[batch * NN + j0 + t];
        __syncthreads();

        float acc[4][4];
        #pragma unroll
        for (int nt = 0; nt < 4; nt++)
            #pragma unroll
            for (int q = 0; q < 4; q++) acc[nt][q] = 0.f;

        #pragma unroll
        for (int k0 = 0; k0 < 64; k0 += 8) {
            unsigned a0, a1, a2, a3;
            {
                const float* base = xs + (mo + gr) * XS_STRIDE + k0 + gc;
                a0 = __float_as_uint(base[0]);
                a1 = __float_as_uint(base[8 * XS_STRIDE]);
                a2 = __float_as_uint(base[4]);
                a3 = __float_as_uint(base[8 * XS_STRIDE + 4]);
            }
            #pragma unroll
            for (int nt = 0; nt < 4; nt++) {
                const float* bb = ys + (no + nt * 8 + gr) * XS_STRIDE + k0 + gc;
                unsigned b0 = __float_as_uint(bb[0]);
                unsigned b1 = __float_as_uint(bb[4]);
                asm volatile(
                    "mma.sync.aligned.m16n8k8.row.col.f32.tf32.tf32.f32 "
                    "{%0,%1,%2,%3}, {%4,%5,%6,%7}, {%8,%9}, {%0,%1,%2,%3};"
                    : "+f"(acc[nt][0]), "+f"(acc[nt][1]), "+f"(acc[nt][2]), "+f"(acc[nt][3])
                    : "r"(a0), "r"(a1), "r"(a2), "r"(a3), "r"(b0), "r"(b1));
            }
        }

        float xi0 = x2s[mo + gr], xi1 = x2s[mo + gr + 8];
        int r0 = i0 + mo + gr, r1 = r0 + 8;
        #pragma unroll
        for (int nt = 0; nt < 4; nt++) {
            int jcd = j0 + no + nt * 8 + gc * 2;
            float yj0 = y2s[no + nt * 8 + gc * 2];
            float yj1 = y2s[no + nt * 8 + gc * 2 + 1];
            float k00 = __expf((2.0f * acc[nt][0] - xi0 - yj0) * INV_EPS);
            float k01 = __expf((2.0f * acc[nt][1] - xi0 - yj1) * INV_EPS);
            float k10 = __expf((2.0f * acc[nt][2] - xi1 - yj0) * INV_EPS);
            float k11 = __expf((2.0f * acc[nt][3] - xi1 - yj1) * INV_EPS);
            *(__nv_bfloat162*)(Kb + (size_t)r0 * NN + jcd) = __floats2bfloat162_rn(k00, k01);
            *(__nv_bfloat162*)(Kb + (size_t)r1 * NN + jcd) = __floats2bfloat162_rn(k10, k11);
        }
    }
}

// ---------------- persistent Sinkhorn: per-batch barriers + overlapped global verdict ----------------
// Block bk: batch = bk>>3, seg = bk&7. Flat grid (no clusters): co-residency proven.
__global__ void __launch_bounds__(TB, 1) sinkhorn_persistent(float* __restrict__ out) {
    int bk  = blockIdx.x;
    int tid = threadIdx.x;
    int batch = bk >> 3;
    int seg   = bk & 7;
    int w = tid >> 5, lane = tid & 31;

    __shared__ float4 vec4[256];        // b (row/cost phases) or a (col phase), fp32
    __shared__ float  rsum[128];
    __shared__ float  cps[64 * 128];    // col-phase partials (32 KB); reused as scratch
    __shared__ int    s_vd;
    float* vecs = (float*)vec4;

    int it = 0;
    for (; it < MAX_ITER; ++it) {
        // ======== row phase: r_i = sum_j K_ij b_j ; update u, a ========
        if (tid < 256) vec4[tid] = ((const float4*)(g_b + batch * NN))[tid];
        __syncthreads();
        {
            int ibase = seg * 128 + w * 4;      // 4 consecutive rows per warp
            const uint4* K0 = (const uint4*)(g_Kh + (size_t)(batch * NN + ibase) * NN);
            float s0 = 0.f, s1 = 0.f, s2 = 0.f, s3 = 0.f;
            #pragma unroll
            for (int k = 0; k < 4; k++) {
                int idx = k * 32 + lane;        // uint4 index within row (8 bf16 each)
                float4 b0 = vec4[idx * 2], b1 = vec4[idx * 2 + 1];
                s0 += dot8(K0[          idx], b0, b1);
                s1 += dot8(K0[128 +     idx], b0, b1);
                s2 += dot8(K0[256 +     idx], b0, b1);
                s3 += dot8(K0[384 +     idx], b0, b1);
            }
            #pragma unroll
            for (int o = 16; o; o >>= 1) {
                s0 += __shfl_xor_sync(0xFFFFFFFFu, s0, o);
                s1 += __shfl_xor_sync(0xFFFFFFFFu, s1, o);
                s2 += __shfl_xor_sync(0xFFFFFFFFu, s2, o);
                s3 += __shfl_xor_sync(0xFFFFFFFFu, s3, o);
            }
            if (lane == 0) {
                rsum[w * 4 + 0] = s0; rsum[w * 4 + 1] = s1;
                rsum[w * 4 + 2] = s2; rsum[w * 4 + 3] = s3;
            }
        }
        __syncthreads();
        if (tid < 128) {
            int gi = batch * NN + seg * 128 + tid;
            float uo = g_u[gi];
            float a  = g_a[gi];
            float lse = logf(fmaf(a, rsum[tid], 1e-6f));   // accurate log: iteration fidelity
            float un  = EPSF * (LOG_MU - lse) + uo;
            g_u[gi] = un;
            g_a[gi] = expf(un * INV_EPS);
            cps[tid] = fabsf(un - uo);
        }
        __syncthreads();
        if (tid < 32) {                // warp-level derr reduction
            float d = cps[tid] + cps[tid + 32] + cps[tid + 64] + cps[tid + 96];
            #pragma unroll
            for (int o = 16; o; o >>= 1) d += __shfl_xor_sync(0xFFFFFFFFu, d, o);
            if (tid == 0) atomicAdd(&g_errA[it * BATCH + batch], d);
        }
        batch_barrier(batch);    // batch's new a + err total complete

        // rank 0 posts batch completion; 16th poster computes the global verdict
        if (seg == 0 && tid == 0) {
            int old = atomicAdd(&g_itcnt[it], 1);
            if (old == BATCH - 1) {
                float e = 0.f;
                #pragma unroll
                for (int bb = 0; bb < BATCH; bb++)
                    e += *((volatile float*)&g_errA[it * BATCH + bb]);
                __threadfence();
                *((volatile int*)&g_verdict[it]) = (e * (1.0f / BATCH) < THRESH) ? 2 : 1;
            }
        }

        // ======== col phase: s_j = sum_i K_ij a_i ; uint4 loads, 8 cols per thread ========
        if (tid < 256) vec4[tid] = ((const float4*)(g_a + batch * NN))[tid];
        __syncthreads();
        {
            int tx4 = tid & 15;            // which uint4 (8 cols) within 128-col segment
            int rg  = tid >> 4;            // 0..63 row group
            const char* Kbase = (const char*)g_Kh
                + (size_t)(batch * NN) * (NN * 2) + seg * 256 + tx4 * 16;
            float a0=0.f,a1=0.f,a2=0.f,a3=0.f,a4=0.f,a5=0.f,a6=0.f,a7=0.f;
            #pragma unroll
            for (int k = 0; k < 16; k++) {
                int i = k * 64 + rg;
                uint4 q = *(const uint4*)(Kbase + (size_t)i * (NN * 2));
                float av = vecs[i];
                float2 p0 = __bfloat1622float2(*(const __nv_bfloat162*)&q.x);
                float2 p1 = __bfloat1622float2(*(const __nv_bfloat162*)&q.y);
                float2 p2 = __bfloat1622float2(*(const __nv_bfloat162*)&q.z);
                float2 p3 = __bfloat1622float2(*(const __nv_bfloat162*)&q.w);
                a0 = fmaf(av, p0.x, a0); a1 = fmaf(av, p0.y, a1);
                a2 = fmaf(av, p1.x, a2); a3 = fmaf(av, p1.y, a3);
                a4 = fmaf(av, p2.x, a4); a5 = fmaf(av, p2.y, a5);
                a6 = fmaf(av, p3.x, a6); a7 = fmaf(av, p3.y, a7);
            }
            float* dst = cps + rg * 128 + tx4 * 8;
            dst[0]=a0; dst[1]=a1; dst[2]=a2; dst[3]=a3;
            dst[4]=a4; dst[5]=a5; dst[6]=a6; dst[7]=a7;
        }
        __syncthreads();
        if (tid < 128) {
            float t0=0.f,t1=0.f,t2=0.f,t3=0.f;
            #pragma unroll
            for (int g = 0; g < 64; g += 4) {
                t0 += cps[(g+0)*128 + tid];
                t1 += cps[(g+1)*128 + tid];
                t2 += cps[(g+2)*128 + tid];
                t3 += cps[(g+3)*128 + tid];
            }
            float s = (t0 + t1) + (t2 + t3);
            int gj = batch * NN + seg * 128 + tid;
            float vo = g_v[gj], b = g_b[gj];
            float vn = EPSF * (LOG_MU - logf(fmaf(b, s, 1e-6f))) + vo;
            g_v[gj] = vn;
            g_b[gj] = expf(vn * INV_EPS);
        }
        batch_barrier(batch);    // batch's new b visible

        // ======== consume global verdict (posted during col phase; rarely spins) ========
        if (tid == 0) {
            int vd, ns = 32;
            while ((vd = *((volatile int*)&g_verdict[it])) == 0) {
                __nanosleep(ns);
                if (ns < 1024) ns <<= 1;
            }
            s_vd = vd;
        }
        __syncthreads();
        if (s_vd == 2) break;
    }

    // ======== cost phase: -eps * sum_ij a_i b_j K_ij ln K_ij ========
    if (tid < 256) vec4[tid] = ((const float4*)(g_b + batch * NN))[tid];
    __syncthreads();
    {
        int ibase = seg * 128 + w * 4;
        const uint4* K0 = (const uint4*)(g_Kh + (size_t)(batch * NN + ibase) * NN);
        float s0 = 0.f, s1 = 0.f, s2 = 0.f, s3 = 0.f;
        #pragma unroll
        for (int k = 0; k < 4; k++) {
            int idx = k * 32 + lane;
            float4 b0 = vec4[idx * 2], b1 = vec4[idx * 2 + 1];
            s0 += dot8log(K0[          idx], b0, b1);
            s1 += dot8log(K0[128 +     idx], b0, b1);
            s2 += dot8log(K0[256 +     idx], b0, b1);
            s3 += dot8log(K0[384 +     idx], b0, b1);
        }
        #pragma unroll
        for (int o = 16; o; o >>= 1) {
            s0 += __shfl_xor_sync(0xFFFFFFFFu, s0, o);
            s1 += __shfl_xor_sync(0xFFFFFFFFu, s1, o);
            s2 += __shfl_xor_sync(0xFFFFFFFFu, s2, o);
            s3 += __shfl_xor_sync(0xFFFFFFFFu, s3, o);
        }
        if (lane == 0) {
            rsum[w * 4 + 0] = s0; rsum[w * 4 + 1] = s1;
            rsum[w * 4 + 2] = s2; rsum[w * 4 + 3] = s3;
        }
    }
    __syncthreads();
    if (tid < 128) {
        int gi = batch * NN + seg * 128 + tid;
        cps[tid] = g_a[gi] * rsum[tid];
    }
    __syncthreads();
    if (tid == 0) {
        float bsum = 0.f;
        #pragma unroll
        for (int k = 0; k < 128; k++) bsum += cps[k];
        atomicAdd(&g_cost, (double)(-EPSF * bsum));
        __threadfence();
        int ticket = atomicAdd(&g_fin, 1);
        if (ticket == GB - 1) {
            __threadfence();
            out[0] = (float)(*((volatile double*)&g_cost) * (1.0 / (double)BATCH));
        }
    }
}

// ---------------- launch ----------------
extern "C" void kernel_launch(void* const* d_in, const int* in_sizes, int n_in,
                              void* d_out, int out_size) {
    const float* x = (const float*)d_in[0];
    const float* y = (const float*)d_in[1];
    float* out = (float*)d_out;
    (void)in_sizes; (void)n_in; (void)out_size;

    softmax_kernel<<<2048, 256>>>(x, y);   // 2 rows/warp softmax + fused init
    buildK_mma<<<1024, 256>>>();           // 64x256 blocks, tf32 HMMA, bf16 K store
    sinkhorn_persistent<<<GB, TB>>>(out);  // per-batch-sync Sinkhorn + cost
}